// round 12
// baseline (speedup 1.0000x reference)
#include <cuda_runtime.h>
#include <cuda_bf16.h>
#include <cstdint>
#include <cstddef>

#define B_SZ 8
#define T_SZ 1024
#define D_SZ 256
#define H_SZ 512
#define M_SZ 1024
#define R_SZ 4

// ---------------------------------------------------------------------------
// Scratch (static device globals -- no runtime allocation allowed)
// ---------------------------------------------------------------------------
__device__ float g_xz[(size_t)B_SZ * T_SZ * 4 * H_SZ];   // 64 MB
__device__ float g_h [(size_t)B_SZ * T_SZ * H_SZ];       // 16 MB
__device__ float g_rk[(size_t)R_SZ * B_SZ * T_SZ * M_SZ];// 128 MB
__device__ float g_wk[(size_t)B_SZ * T_SZ * M_SZ];       // 32 MB
__device__ float g_eb[(size_t)B_SZ * T_SZ * M_SZ];       // 32 MB
__device__ float g_ab[(size_t)B_SZ * T_SZ * M_SZ];       // 32 MB
__device__ float g_sim [R_SZ * B_SZ * T_SZ];
__device__ float g_simw[B_SZ * T_SZ];
__device__ float g_ww  [B_SZ * T_SZ];
__device__ float g_invn[M_SZ];
__device__ float g_colsum[M_SZ];
__device__ unsigned g_bar;
// bf16-split operands: A' = [hi(h) | lo(h)]  (8192 x 1024 bf16)
__device__ __nv_bfloat16 g_asp[(size_t)B_SZ * T_SZ * 2 * H_SZ];
// B' = per-matrix transposed [hi(W^T) | lo(W^T)]  (7 x 1024 x 1024 bf16)
__device__ __nv_bfloat16 g_bsp[(size_t)7 * M_SZ * 2 * H_SZ];

#define SMEM_SWZ(off) ((off) ^ (((off) >> 3) & 0x70))

__device__ __forceinline__ uint32_t smem_u32(const void* p) {
    uint32_t a;
    asm("{ .reg .u64 t; cvta.to.shared.u64 t, %1; cvt.u32.u64 %0, t; }"
        : "=r"(a) : "l"(p));
    return a;
}

// ---------------------------------------------------------------------------
// Block-wide reductions (blockDim.x == 256)
// ---------------------------------------------------------------------------
__device__ __forceinline__ float blockReduceSum(float v) {
    __shared__ float sh[8];
    int lane = threadIdx.x & 31, w = threadIdx.x >> 5;
#pragma unroll
    for (int o = 16; o; o >>= 1) v += __shfl_xor_sync(0xffffffffu, v, o);
    if (lane == 0) sh[w] = v;
    __syncthreads();
    if (w == 0) {
        float x = (lane < 8) ? sh[lane] : 0.f;
#pragma unroll
        for (int o = 4; o; o >>= 1) x += __shfl_xor_sync(0xffffffffu, x, o);
        if (lane == 0) sh[0] = x;
    }
    __syncthreads();
    float r = sh[0];
    __syncthreads();
    return r;
}
__device__ __forceinline__ float blockReduceMax(float v) {
    __shared__ float sh[8];
    int lane = threadIdx.x & 31, w = threadIdx.x >> 5;
#pragma unroll
    for (int o = 16; o; o >>= 1) v = fmaxf(v, __shfl_xor_sync(0xffffffffu, v, o));
    if (lane == 0) sh[w] = v;
    __syncthreads();
    if (w == 0) {
        float x = (lane < 8) ? sh[lane] : -3.402823466e38f;
#pragma unroll
        for (int o = 4; o; o >>= 1) x = fmaxf(x, __shfl_xor_sync(0xffffffffu, x, o));
        if (lane == 0) sh[0] = x;
    }
    __syncthreads();
    float r = sh[0];
    __syncthreads();
    return r;
}
__device__ __forceinline__ float sigmoidf_(float x) {
    return 1.f / (1.f + __expf(-x));
}

// ---------------------------------------------------------------------------
// fp32 SGEMM (xz = inputs @ Wx + b; proven)
// ---------------------------------------------------------------------------
__global__ void __launch_bounds__(256) sgemm_kernel(
    const float* __restrict__ A, const float* __restrict__ B,
    const float* __restrict__ bias, float* __restrict__ C, int N, int K)
{
    const int n0 = blockIdx.x * 128;
    const int m0 = blockIdx.y * 128;
    __shared__ float As[8][128];
    __shared__ float Bs[8][128];
    const int tid  = threadIdx.x;
    const int arow = tid >> 1, ak = (tid & 1) * 4;
    const int bk   = tid >> 5, bc = (tid & 31) * 4;
    const int tx   = tid & 15, ty = tid >> 4;
    const float* Ap = A + (size_t)(m0 + arow) * K + ak;
    const float* Bp = B + (size_t)bk * N + n0 + bc;
    float4 aR = *(const float4*)Ap;
    float4 bR = *(const float4*)Bp;
    float acc[8][8];
#pragma unroll
    for (int i = 0; i < 8; i++)
#pragma unroll
        for (int j = 0; j < 8; j++) acc[i][j] = 0.f;
    const int KT = K >> 3;
    for (int kt = 0; kt < KT; kt++) {
        As[ak + 0][arow] = aR.x; As[ak + 1][arow] = aR.y;
        As[ak + 2][arow] = aR.z; As[ak + 3][arow] = aR.w;
        *(float4*)&Bs[bk][bc] = bR;
        __syncthreads();
        if (kt + 1 < KT) {
            aR = *(const float4*)(Ap + (kt + 1) * 8);
            bR = *(const float4*)(Bp + (size_t)(kt + 1) * 8 * N);
        }
#pragma unroll
        for (int kk = 0; kk < 8; kk++) {
            float4 a0 = *(const float4*)&As[kk][ty * 4];
            float4 a1 = *(const float4*)&As[kk][64 + ty * 4];
            float4 b0 = *(const float4*)&Bs[kk][tx * 4];
            float4 b1 = *(const float4*)&Bs[kk][64 + tx * 4];
            float ar[8] = {a0.x, a0.y, a0.z, a0.w, a1.x, a1.y, a1.z, a1.w};
            float br[8] = {b0.x, b0.y, b0.z, b0.w, b1.x, b1.y, b1.z, b1.w};
#pragma unroll
            for (int i = 0; i < 8; i++)
#pragma unroll
                for (int j = 0; j < 8; j++) acc[i][j] += ar[i] * br[j];
        }
        __syncthreads();
    }
    float4 bias0 = *(const float4*)&bias[n0 + tx * 4];
    float4 bias1 = *(const float4*)&bias[n0 + 64 + tx * 4];
    float bb[8] = {bias0.x, bias0.y, bias0.z, bias0.w,
                   bias1.x, bias1.y, bias1.z, bias1.w};
#pragma unroll
    for (int i = 0; i < 8; i++) {
        int row = m0 + ((i < 4) ? (ty * 4 + i) : (64 + ty * 4 + (i - 4)));
        float4 o0 = make_float4(acc[i][0] + bb[0], acc[i][1] + bb[1],
                                acc[i][2] + bb[2], acc[i][3] + bb[3]);
        float4 o1 = make_float4(acc[i][4] + bb[4], acc[i][5] + bb[5],
                                acc[i][6] + bb[6], acc[i][7] + bb[7]);
        *(float4*)&C[(size_t)row * N + n0 + tx * 4]      = o0;
        *(float4*)&C[(size_t)row * N + n0 + 64 + tx * 4] = o1;
    }
}

// ---------------------------------------------------------------------------
// Persistent LSTM: 64 CTAs x 512 threads (half the barrier participants).
// CTA cb owns units u0 = cb*8 .. +8 (32 Wh cols) for all 8 batches;
// 32 W regs/thread (same as proven R5). Single-counter barrier, target 64/step.
// ---------------------------------------------------------------------------
__global__ void __launch_bounds__(512, 1) lstm_kernel(
    const float* __restrict__ xz, const float* __restrict__ Wh,
    float* __restrict__ h_out)
{
    const int cb = blockIdx.x;        // 0..63
    const int u0 = cb * 8;
    const int tid = threadIdx.x;
    const int uu = tid >> 6;          // 0..7 (unit within CTA)
    const int ks = tid & 63;          // 0..63 (k-chunk of 8)
    const int k0 = ks * 8;
    const int lane = tid & 31;
    const int half = (tid >> 5) & 1;

    // W[g][kk] = Wh[k0+kk][g*512 + u0+uu]
    float W[4][8];
#pragma unroll
    for (int g = 0; g < 4; g++)
#pragma unroll
        for (int kk = 0; kk < 8; kk++)
            W[g][kk] = Wh[(size_t)(k0 + kk) * 2048 + g * 512 + u0 + uu];

    __shared__ float h_s[B_SZ * H_SZ];   // 16 KB
    __shared__ float red_s[8][2][32];    // [uu][half][v], v = b*4+g

    const bool owner = (tid < 64);
    const int ob = tid >> 3;   // owner batch (0..7)
    const int ou = tid & 7;    // owner unit  (0..7)
    float c_reg = 0.f;

    for (int t = 0; t < T_SZ; t++) {
        float xzr0 = 0.f, xzr1 = 0.f, xzr2 = 0.f, xzr3 = 0.f;
        if (owner) {
            const float* p = xz + ((size_t)(ob * T_SZ + t)) * 2048 + u0 + ou;
            xzr0 = p[0]; xzr1 = p[512]; xzr2 = p[1024]; xzr3 = p[1536];
        }

        if (t > 0) {
            // load h_{t-1} (all batches) into smem: 1024 float4 over 512 thr
            {
                const float4* src = (const float4*)h_out;
                float4* dst = (float4*)h_s;
#pragma unroll
                for (int j = 0; j < 2; j++) {
                    int i4 = tid + j * 512;            // 0..1023
                    int b = i4 >> 7, kk4 = i4 & 127;
                    dst[i4] = src[((size_t)b * T_SZ + (t - 1)) * 128 + kk4];
                }
            }
            __syncthreads();

            float A[32];
#pragma unroll
            for (int v = 0; v < 32; v++) A[v] = 0.f;
#pragma unroll
            for (int b = 0; b < 8; b++) {
                const float4* hp4 = (const float4*)(h_s + b * 512 + k0);
                float4 h0 = hp4[0], h1 = hp4[1];
                float hv[8] = {h0.x, h0.y, h0.z, h0.w, h1.x, h1.y, h1.z, h1.w};
#pragma unroll
                for (int g = 0; g < 4; g++)
#pragma unroll
                    for (int kk = 0; kk < 8; kk++)
                        A[b * 4 + g] += hv[kk] * W[g][kk];
            }
            // Butterfly multi-reduce: 32 values across 32 lanes
#pragma unroll
            for (int o = 16; o >= 1; o >>= 1) {
                const bool hi = (lane & o) != 0;
#pragma unroll
                for (int v = 0; v < 16; v++) {
                    if (v < o) {
                        float lo_v = A[v], hi_v = A[v + o];
                        float send = hi ? lo_v : hi_v;
                        float recv = __shfl_xor_sync(0xffffffffu, send, o);
                        A[v] = (hi ? hi_v : lo_v) + recv;
                    }
                }
            }
            red_s[uu][half][lane] = A[0];
            __syncthreads();
        }

        if (owner) {
            float zi = xzr0, zf = xzr1, zg = xzr2, zo = xzr3;
            if (t > 0) {
                int vb = ob * 4;
                zi += red_s[ou][0][vb + 0] + red_s[ou][1][vb + 0];
                zf += red_s[ou][0][vb + 1] + red_s[ou][1][vb + 1];
                zg += red_s[ou][0][vb + 2] + red_s[ou][1][vb + 2];
                zo += red_s[ou][0][vb + 3] + red_s[ou][1][vb + 3];
            }
            float ig = sigmoidf_(zi);
            float fg = sigmoidf_(zf);
            float gg = tanhf(zg);
            float og = sigmoidf_(zo);
            c_reg = fg * c_reg + ig * gg;
            float hval = og * tanhf(c_reg);
            h_out[((size_t)ob * T_SZ + t) * H_SZ + u0 + ou] = hval;
        }

        if (t < T_SZ - 1) {
            __syncthreads();
            if (tid == 0) {
                asm volatile("red.release.gpu.global.add.u32 [%0], %1;"
                             :: "l"(&g_bar), "r"(1u) : "memory");
                const unsigned target = (unsigned)(t + 1) * 64u;
                unsigned v;
                do {
                    asm volatile("ld.acquire.gpu.global.u32 %0, [%1];"
                                 : "=r"(v) : "l"(&g_bar) : "memory");
                } while (v < target);
            }
            __syncthreads();
        }
    }
}

__global__ void reset_kernel() {
    if (threadIdx.x == 0) g_bar = 0u;
}

// ---------------------------------------------------------------------------
// bf16 split kernels
// ---------------------------------------------------------------------------
__global__ void split_h_kernel(const float* __restrict__ h) {
    size_t id = (size_t)blockIdx.x * 256 + threadIdx.x;   // over 8192*512
    int m = (int)(id >> 9), k = (int)(id & 511);
    float a = h[id];
    __nv_bfloat16 hi = __float2bfloat16(a);
    __nv_bfloat16 lo = __float2bfloat16(a - __bfloat162float(hi));
    g_asp[(size_t)m * 1024 + k]       = hi;
    g_asp[(size_t)m * 1024 + 512 + k] = lo;
}
__global__ void split_w_kernel(const float* __restrict__ rk_W,
                               const float* __restrict__ wk_W,
                               const float* __restrict__ we_W,
                               const float* __restrict__ wa_W)
{
    size_t id = (size_t)blockIdx.x * 256 + threadIdx.x;   // over 7*512*1024
    int mat = (int)(id / (512 * 1024));
    int r2  = (int)(id % (512 * 1024));
    int k = r2 >> 10, n = r2 & 1023;
    const float* W;
    if (mat < 4)       W = rk_W + (size_t)mat * 512 * 1024;
    else if (mat == 4) W = wk_W;
    else if (mat == 5) W = we_W;
    else               W = wa_W;
    float a = W[(size_t)k * 1024 + n];
    __nv_bfloat16 hi = __float2bfloat16(a);
    __nv_bfloat16 lo = __float2bfloat16(a - __bfloat162float(hi));
    __nv_bfloat16* dst = g_bsp + (size_t)mat * 1024 * 1024 + (size_t)n * 1024;
    dst[k]       = hi;
    dst[512 + k] = lo;
}

// ---------------------------------------------------------------------------
// mma.sync bf16-split projection GEMM (fallback HMMA path; legal at sm_100).
// 128x128 tile/CTA, 256 thr = 8 warps (4m x 2n), warp tile 32x64.
// K' = 1536: A'=[Ah,Ah,Al], B'=[Bh,Bl,Bh]; fp32 accumulators.
// ---------------------------------------------------------------------------
#define KC 64
#define NCH 24    // 1536/64
__global__ void __launch_bounds__(256) mma_proj_kernel(
    const float* __restrict__ rk_b, const float* __restrict__ wk_b,
    const float* __restrict__ we_b, const float* __restrict__ wa_b,
    float* __restrict__ rk_out, float* __restrict__ wk_out,
    float* __restrict__ eb_out, float* __restrict__ ab_out)
{
    const int tix = blockIdx.x;            // 7 * 64 * 8
    const int mat = tix >> 9;
    const int rem = tix & 511;
    const int mt  = rem >> 3;
    const int nt  = rem & 7;
    const int m0  = mt * 128;
    const int n0  = nt * 128;

    const __nv_bfloat16* Bmat = g_bsp + (size_t)mat * 1024 * 1024;
    float* C; const float* bias;
    if (mat < 4)       { C = rk_out + (size_t)mat * 8192 * 1024; bias = rk_b + mat * 1024; }
    else if (mat == 4) { C = wk_out; bias = wk_b; }
    else if (mat == 5) { C = eb_out; bias = we_b; }
    else               { C = ab_out; bias = wa_b; }

    // SMEM: A tile 128x64 bf16 (128B rows, SW128) + B tile same = 32KB
    __shared__ __align__(128) __nv_bfloat16 As[128 * KC];
    __shared__ __align__(128) __nv_bfloat16 Bs[128 * KC];
    const uint32_t AsU = smem_u32(As);
    const uint32_t BsU = smem_u32(Bs);

    const int tid  = threadIdx.x;
    const int wid  = tid >> 5, lane = tid & 31;
    const int wm   = wid & 3;          // warp m index (0..3)
    const int wn   = wid >> 2;         // warp n index (0..1)

    // gmem load mapping: row = tid>>1 (0..127), half-row = tid&1 (4 x 16B)
    const int lrow = tid >> 1;
    const int lhalf = tid & 1;
    const uint4* A4 = (const uint4*)g_asp;    // row pitch 128 uint4 (2048B)
    const uint4* B4 = (const uint4*)Bmat;

    float d[2][8][4];
#pragma unroll
    for (int i = 0; i < 2; i++)
#pragma unroll
        for (int j = 0; j < 8; j++)
#pragma unroll
            for (int q = 0; q < 4; q++) d[i][j][q] = 0.f;

    uint4 aR[4], bR[4];
    // prologue load chunk 0 (acol=0, bcol=0)
#pragma unroll
    for (int i = 0; i < 4; i++) {
        aR[i] = A4[(size_t)(m0 + lrow) * 128 + lhalf * 4 + i];
        bR[i] = B4[(size_t)(n0 + lrow) * 128 + lhalf * 4 + i];
    }

    for (int c = 0; c < NCH; c++) {
        // store staged regs into swizzled smem
#pragma unroll
        for (int i = 0; i < 4; i++) {
            uint32_t off = lrow * 128 + (lhalf * 4 + i) * 16;
            uint32_t sw = SMEM_SWZ(off);
            *(uint4*)((char*)As + sw) = aR[i];
            *(uint4*)((char*)Bs + sw) = bR[i];
        }
        __syncthreads();

        // prefetch next chunk
        if (c + 1 < NCH) {
            int kb = (c + 1) * KC;
            int acol = (kb < 512) ? kb : kb - 512;      // [Ah,Ah,Al]
            int bcol = (kb < 1024) ? kb : kb - 1024;    // [Bh,Bl,Bh]
#pragma unroll
            for (int i = 0; i < 4; i++) {
                aR[i] = A4[(size_t)(m0 + lrow) * 128 + (acol >> 3) + lhalf * 4 + i];
                bR[i] = B4[(size_t)(n0 + lrow) * 128 + (bcol >> 3) + lhalf * 4 + i];
            }
        }

        // MMA over 4 k16 steps
#pragma unroll
        for (int ksi = 0; ksi < 4; ksi++) {
            uint32_t a0[4], a1[4];
            {
                // A frag i=0: rows wm*32 + (lane&15); i=1: +16
                int row = wm * 32 + (lane & 15);
                uint32_t off = (uint32_t)row * 128 + ksi * 32 + (lane >> 4) * 16;
                uint32_t ad = AsU + SMEM_SWZ(off);
                asm volatile("ldmatrix.sync.aligned.m8n8.x4.shared.b16 {%0,%1,%2,%3}, [%4];"
                             : "=r"(a0[0]), "=r"(a0[1]), "=r"(a0[2]), "=r"(a0[3]) : "r"(ad));
                off = (uint32_t)(row + 16) * 128 + ksi * 32 + (lane >> 4) * 16;
                ad = AsU + SMEM_SWZ(off);
                asm volatile("ldmatrix.sync.aligned.m8n8.x4.shared.b16 {%0,%1,%2,%3}, [%4];"
                             : "=r"(a1[0]), "=r"(a1[1]), "=r"(a1[2]), "=r"(a1[3]) : "r"(ad));
            }
#pragma unroll
            for (int j = 0; j < 8; j++) {
                uint32_t b0[2];
                int brow = wn * 64 + j * 8 + (lane & 7);
                uint32_t off = (uint32_t)brow * 128 + ksi * 32 + ((lane >> 3) & 1) * 16;
                uint32_t bd = BsU + SMEM_SWZ(off);
                asm volatile("ldmatrix.sync.aligned.m8n8.x2.shared.b16 {%0,%1}, [%2];"
                             : "=r"(b0[0]), "=r"(b0[1]) : "r"(bd));
                asm volatile("mma.sync.aligned.m16n8k16.row.col.f32.bf16.bf16.f32 "
                             "{%0,%1,%2,%3}, {%4,%5,%6,%7}, {%8,%9}, {%0,%1,%2,%3};"
                             : "+f"(d[0][j][0]), "+f"(d[0][j][1]),
                               "+f"(d[0][j][2]), "+f"(d[0][j][3])
                             : "r"(a0[0]), "r"(a0[1]), "r"(a0[2]), "r"(a0[3]),
                               "r"(b0[0]), "r"(b0[1]));
                asm volatile("mma.sync.aligned.m16n8k16.row.col.f32.bf16.bf16.f32 "
                             "{%0,%1,%2,%3}, {%4,%5,%6,%7}, {%8,%9}, {%0,%1,%2,%3};"
                             : "+f"(d[1][j][0]), "+f"(d[1][j][1]),
                               "+f"(d[1][j][2]), "+f"(d[1][j][3])
                             : "r"(a1[0]), "r"(a1[1]), "r"(a1[2]), "r"(a1[3]),
                               "r"(b0[0]), "r"(b0[1]));
            }
        }
        __syncthreads();
    }

    // Epilogue: lane (r0, c0) owns rows {r0, r0+8} x cols {c0, c0+1} per frag
    const int r0 = lane >> 2;
    const int c0 = (lane & 3) * 2;
#pragma unroll
    for (int i = 0; i < 2; i++) {
#pragma unroll
        for (int j = 0; j < 8; j++) {
            int col = n0 + wn * 64 + j * 8 + c0;
            float b0v = bias[col], b1v = bias[col + 1];
            int rowA = m0 + wm * 32 + i * 16 + r0;
            float2 v0 = make_float2(d[i][j][0] + b0v, d[i][j][1] + b1v);
            float2 v1 = make_float2(d[i][j][2] + b0v, d[i][j][3] + b1v);
            *(float2*)&C[(size_t)rowA * 1024 + col]       = v0;
            *(float2*)&C[(size_t)(rowA + 8) * 1024 + col] = v1;
        }
    }
}

// ---------------------------------------------------------------------------
// memory row inverse-norms and column sums
// ---------------------------------------------------------------------------
__global__ void rownorm_kernel(const float* __restrict__ mem) {
    int t = blockIdx.x;
    float4 v = ((const float4*)(mem + (size_t)t * M_SZ))[threadIdx.x];
    float ss = v.x * v.x + v.y * v.y + v.z * v.z + v.w * v.w;
    ss = blockReduceSum(ss);
    if (threadIdx.x == 0) g_invn[t] = rsqrtf(fmaxf(ss, 1e-12f));
}
__global__ void colsum_kernel(const float* __restrict__ mem) {
    int j = blockIdx.x * 256 + threadIdx.x;
    float s = 0.f;
    for (int i = 0; i < M_SZ; i++) s += mem[(size_t)i * M_SZ + j];
    g_colsum[j] = s;
}

// ---------------------------------------------------------------------------
// sim / softmax / memupd (unchanged)
// ---------------------------------------------------------------------------
__global__ void sim_kernel(const float* __restrict__ logits,
                           const float* __restrict__ mem,
                           float* __restrict__ simout)
{
    int row = blockIdx.x;
    int t = row & (T_SZ - 1);
    float4 xv = ((const float4*)(logits + (size_t)row * M_SZ))[threadIdx.x];
    float m = fmaxf(fmaxf(xv.x, xv.y), fmaxf(xv.z, xv.w));
    m = blockReduceMax(m);
    float e0 = __expf(xv.x - m), e1 = __expf(xv.y - m);
    float e2 = __expf(xv.z - m), e3 = __expf(xv.w - m);
    float4 mv = ((const float4*)(mem + (size_t)t * M_SZ))[threadIdx.x];
    float se2 = e0 * e0 + e1 * e1 + e2 * e2 + e3 * e3;
    float sd  = e0 * mv.x + e1 * mv.y + e2 * mv.z + e3 * mv.w;
    se2 = blockReduceSum(se2);
    sd  = blockReduceSum(sd);
    if (threadIdx.x == 0)
        simout[row] = -sd * g_invn[t] * rsqrtf(fmaxf(se2, 1e-12f));
}
__global__ void softmax_row_kernel(const float* __restrict__ in,
                                   const float* __restrict__ scale,
                                   float* __restrict__ out)
{
    int r = blockIdx.x;
    float4 xv = ((const float4*)(in + (size_t)r * 1024))[threadIdx.x];
    float m = fmaxf(fmaxf(xv.x, xv.y), fmaxf(xv.z, xv.w));
    m = blockReduceMax(m);
    float e0 = __expf(xv.x - m), e1 = __expf(xv.y - m);
    float e2 = __expf(xv.z - m), e3 = __expf(xv.w - m);
    float S = blockReduceSum(e0 + e1 + e2 + e3);
    float inv = 1.f / S;
    float4 o = make_float4(e0 * inv, e1 * inv, e2 * inv, e3 * inv);
    if (scale) {
        float4 cs = ((const float4*)scale)[threadIdx.x];
        o.x *= cs.x; o.y *= cs.y; o.z *= cs.z; o.w *= cs.w;
    }
    ((float4*)(out + (size_t)r * 1024))[threadIdx.x] = o;
}
__global__ void memupd_kernel(const float* __restrict__ eb,
                              const float* __restrict__ ab,
                              const float* __restrict__ mem,
                              float* __restrict__ out)
{
    size_t idx = (size_t)blockIdx.x * blockDim.x + threadIdx.x;
    size_t flat = idx * 4;
    int b   = (int)(flat >> 20);
    int rem = (int)(flat & 0xFFFFFu);
    int i = rem >> 10;
    int j = rem & 1023;
    float4 e = ((const float4*)eb)[idx];
    float4 a = ((const float4*)ab)[idx];
    float4 m = *(const float4*)(mem + (size_t)i * M_SZ + j);
    float4 w = *(const float4*)(g_ww + b * 1024 + j);
    float4 o;
    o.x = (1.f - w.x * sigmoidf_(e.x)) * m.x + w.x * a.x;
    o.y = (1.f - w.y * sigmoidf_(e.y)) * m.y + w.y * a.y;
    o.z = (1.f - w.z * sigmoidf_(e.z)) * m.z + w.z * a.z;
    o.w = (1.f - w.w * sigmoidf_(e.w)) * m.w + w.w * a.w;
    ((float4*)out)[idx] = o;
}

// ---------------------------------------------------------------------------
// Launch
// ---------------------------------------------------------------------------
extern "C" void kernel_launch(void* const* d_in, const int* in_sizes, int n_in,
                              void* d_out, int out_size)
{
    (void)in_sizes; (void)n_in; (void)out_size;
    const float* inputs = (const float*)d_in[0];
    const float* memory = (const float*)d_in[1];
    const float* Wx     = (const float*)d_in[2];
    const float* Wh     = (const float*)d_in[3];
    const float* bvec   = (const float*)d_in[4];
    const float* rk_W   = (const float*)d_in[5];
    const float* rk_b   = (const float*)d_in[6];
    const float* wk_W   = (const float*)d_in[7];
    const float* wk_b   = (const float*)d_in[8];
    const float* we_W   = (const float*)d_in[9];
    const float* we_b   = (const float*)d_in[10];
    const float* wa_W   = (const float*)d_in[11];
    const float* wa_b   = (const float*)d_in[12];
    float* out = (float*)d_out;

    float *xz, *h, *rk, *wk, *eb, *ab, *sim, *simw, *ww, *colsum;
    cudaGetSymbolAddress((void**)&xz,   g_xz);
    cudaGetSymbolAddress((void**)&h,    g_h);
    cudaGetSymbolAddress((void**)&rk,   g_rk);
    cudaGetSymbolAddress((void**)&wk,   g_wk);
    cudaGetSymbolAddress((void**)&eb,   g_eb);
    cudaGetSymbolAddress((void**)&ab,   g_ab);
    cudaGetSymbolAddress((void**)&sim,  g_sim);
    cudaGetSymbolAddress((void**)&simw, g_simw);
    cudaGetSymbolAddress((void**)&ww,   g_ww);
    cudaGetSymbolAddress((void**)&colsum, g_colsum);

    const int MROWS = B_SZ * T_SZ; // 8192

    reset_kernel<<<1, 32>>>();
    rownorm_kernel<<<M_SZ, 256>>>(memory);
    colsum_kernel<<<M_SZ / 256, 256>>>(memory);

    // weight splits (independent of h)
    split_w_kernel<<<7 * 512 * 1024 / 256, 256>>>(rk_W, wk_W, we_W, wa_W);

    // xz = inputs @ Wx + b  (fp32 FFMA)
    sgemm_kernel<<<dim3(2048 / 128, MROWS / 128), 256>>>(
        inputs, Wx, bvec, xz, 2048, 256);

    // LSTM scan -> h  (64 CTAs x 512 threads)
    lstm_kernel<<<64, 512>>>(xz, Wh, h);

    // split h into bf16 hi/lo
    split_h_kernel<<<MROWS * H_SZ / 256, 256>>>(h);

    // all 7 projection GEMMs via mma.sync bf16 split
    mma_proj_kernel<<<7 * 512, 256>>>(rk_b, wk_b, we_b, wa_b, rk, wk, eb, ab);

    // similarity reductions
    sim_kernel<<<R_SZ * B_SZ * T_SZ, 256>>>(rk, memory, sim);
    sim_kernel<<<B_SZ * T_SZ, 256>>>(wk, memory, simw);

    // reads -> out[0:32768)
    softmax_row_kernel<<<R_SZ * B_SZ, 256>>>(sim, colsum, out);
    softmax_row_kernel<<<B_SZ, 256>>>(simw, (const float*)nullptr, ww);

    // new_memory -> out[32768 : ]
    memupd_kernel<<<(B_SZ * M_SZ * M_SZ / 4) / 256, 256>>>(
        eb, ab, memory, out + R_SZ * B_SZ * T_SZ);
}

// round 14
// speedup vs baseline: 1.1696x; 1.1696x over previous
#include <cuda_runtime.h>
#include <cuda_bf16.h>
#include <cstdint>
#include <cstddef>

#define B_SZ 8
#define T_SZ 1024
#define D_SZ 256
#define H_SZ 512
#define M_SZ 1024
#define R_SZ 4

// ---------------------------------------------------------------------------
// Scratch (static device globals -- no runtime allocation allowed)
// ---------------------------------------------------------------------------
__device__ float g_xz[(size_t)B_SZ * T_SZ * 4 * H_SZ];   // 64 MB
__device__ float g_h [(size_t)B_SZ * T_SZ * H_SZ];       // 16 MB
__device__ float g_rk[(size_t)R_SZ * B_SZ * T_SZ * M_SZ];// 128 MB
__device__ float g_wk[(size_t)B_SZ * T_SZ * M_SZ];       // 32 MB
__device__ float g_eb[(size_t)B_SZ * T_SZ * M_SZ];       // 32 MB
__device__ float g_ab[(size_t)B_SZ * T_SZ * M_SZ];       // 32 MB
__device__ float g_sim [R_SZ * B_SZ * T_SZ];
__device__ float g_simw[B_SZ * T_SZ];
__device__ float g_ww  [B_SZ * T_SZ];
__device__ float g_invn[M_SZ];
__device__ float g_colsum[M_SZ];
__device__ unsigned g_bar;
// bf16-split operands: A' = [hi(h) | lo(h)]  (8192 x 1024 bf16)
__device__ __nv_bfloat16 g_asp[(size_t)B_SZ * T_SZ * 2 * H_SZ];
// B' = per-matrix transposed [hi(W^T) | lo(W^T)]  (7 x 1024 x 1024 bf16)
__device__ __nv_bfloat16 g_bsp[(size_t)7 * M_SZ * 2 * H_SZ];

#define SMEM_SWZ(off) ((off) ^ (((off) >> 3) & 0x70))

__device__ __forceinline__ uint32_t smem_u32(const void* p) {
    uint32_t a;
    asm("{ .reg .u64 t; cvta.to.shared.u64 t, %1; cvt.u32.u64 %0, t; }"
        : "=r"(a) : "l"(p));
    return a;
}

// ---------------------------------------------------------------------------
// Block-wide reductions (blockDim.x == 256)
// ---------------------------------------------------------------------------
__device__ __forceinline__ float blockReduceSum(float v) {
    __shared__ float sh[8];
    int lane = threadIdx.x & 31, w = threadIdx.x >> 5;
#pragma unroll
    for (int o = 16; o; o >>= 1) v += __shfl_xor_sync(0xffffffffu, v, o);
    if (lane == 0) sh[w] = v;
    __syncthreads();
    if (w == 0) {
        float x = (lane < 8) ? sh[lane] : 0.f;
#pragma unroll
        for (int o = 4; o; o >>= 1) x += __shfl_xor_sync(0xffffffffu, x, o);
        if (lane == 0) sh[0] = x;
    }
    __syncthreads();
    float r = sh[0];
    __syncthreads();
    return r;
}
__device__ __forceinline__ float blockReduceMax(float v) {
    __shared__ float sh[8];
    int lane = threadIdx.x & 31, w = threadIdx.x >> 5;
#pragma unroll
    for (int o = 16; o; o >>= 1) v = fmaxf(v, __shfl_xor_sync(0xffffffffu, v, o));
    if (lane == 0) sh[w] = v;
    __syncthreads();
    if (w == 0) {
        float x = (lane < 8) ? sh[lane] : -3.402823466e38f;
#pragma unroll
        for (int o = 4; o; o >>= 1) x = fmaxf(x, __shfl_xor_sync(0xffffffffu, x, o));
        if (lane == 0) sh[0] = x;
    }
    __syncthreads();
    float r = sh[0];
    __syncthreads();
    return r;
}
__device__ __forceinline__ float sigmoidf_(float x) {
    return 1.f / (1.f + __expf(-x));
}

// ---------------------------------------------------------------------------
// fp32 SGEMM (xz = inputs @ Wx + b; proven)
// ---------------------------------------------------------------------------
__global__ void __launch_bounds__(256) sgemm_kernel(
    const float* __restrict__ A, const float* __restrict__ B,
    const float* __restrict__ bias, float* __restrict__ C, int N, int K)
{
    const int n0 = blockIdx.x * 128;
    const int m0 = blockIdx.y * 128;
    __shared__ float As[8][128];
    __shared__ float Bs[8][128];
    const int tid  = threadIdx.x;
    const int arow = tid >> 1, ak = (tid & 1) * 4;
    const int bk   = tid >> 5, bc = (tid & 31) * 4;
    const int tx   = tid & 15, ty = tid >> 4;
    const float* Ap = A + (size_t)(m0 + arow) * K + ak;
    const float* Bp = B + (size_t)bk * N + n0 + bc;
    float4 aR = *(const float4*)Ap;
    float4 bR = *(const float4*)Bp;
    float acc[8][8];
#pragma unroll
    for (int i = 0; i < 8; i++)
#pragma unroll
        for (int j = 0; j < 8; j++) acc[i][j] = 0.f;
    const int KT = K >> 3;
    for (int kt = 0; kt < KT; kt++) {
        As[ak + 0][arow] = aR.x; As[ak + 1][arow] = aR.y;
        As[ak + 2][arow] = aR.z; As[ak + 3][arow] = aR.w;
        *(float4*)&Bs[bk][bc] = bR;
        __syncthreads();
        if (kt + 1 < KT) {
            aR = *(const float4*)(Ap + (kt + 1) * 8);
            bR = *(const float4*)(Bp + (size_t)(kt + 1) * 8 * N);
        }
#pragma unroll
        for (int kk = 0; kk < 8; kk++) {
            float4 a0 = *(const float4*)&As[kk][ty * 4];
            float4 a1 = *(const float4*)&As[kk][64 + ty * 4];
            float4 b0 = *(const float4*)&Bs[kk][tx * 4];
            float4 b1 = *(const float4*)&Bs[kk][64 + tx * 4];
            float ar[8] = {a0.x, a0.y, a0.z, a0.w, a1.x, a1.y, a1.z, a1.w};
            float br[8] = {b0.x, b0.y, b0.z, b0.w, b1.x, b1.y, b1.z, b1.w};
#pragma unroll
            for (int i = 0; i < 8; i++)
#pragma unroll
                for (int j = 0; j < 8; j++) acc[i][j] += ar[i] * br[j];
        }
        __syncthreads();
    }
    float4 bias0 = *(const float4*)&bias[n0 + tx * 4];
    float4 bias1 = *(const float4*)&bias[n0 + 64 + tx * 4];
    float bb[8] = {bias0.x, bias0.y, bias0.z, bias0.w,
                   bias1.x, bias1.y, bias1.z, bias1.w};
#pragma unroll
    for (int i = 0; i < 8; i++) {
        int row = m0 + ((i < 4) ? (ty * 4 + i) : (64 + ty * 4 + (i - 4)));
        float4 o0 = make_float4(acc[i][0] + bb[0], acc[i][1] + bb[1],
                                acc[i][2] + bb[2], acc[i][3] + bb[3]);
        float4 o1 = make_float4(acc[i][4] + bb[4], acc[i][5] + bb[5],
                                acc[i][6] + bb[6], acc[i][7] + bb[7]);
        *(float4*)&C[(size_t)row * N + n0 + tx * 4]      = o0;
        *(float4*)&C[(size_t)row * N + n0 + 64 + tx * 4] = o1;
    }
}

// ---------------------------------------------------------------------------
// Persistent LSTM (R5, 128 CTAs x 256 threads — proven fastest config)
// ---------------------------------------------------------------------------
__global__ void __launch_bounds__(256, 1) lstm_kernel(
    const float* __restrict__ xz, const float* __restrict__ Wh,
    float* __restrict__ h_out)
{
    const int cb = blockIdx.x;
    const int u0 = cb * 4;
    const int tid = threadIdx.x;
    const int uu = tid >> 6;
    const int ks = tid & 63;
    const int k0 = ks * 8;
    const int lane = tid & 31;
    const int half = (tid >> 5) & 1;

    float W[4][8];
#pragma unroll
    for (int g = 0; g < 4; g++)
#pragma unroll
        for (int kk = 0; kk < 8; kk++)
            W[g][kk] = Wh[(size_t)(k0 + kk) * 2048 + g * 512 + u0 + uu];

    __shared__ float h_s[B_SZ * H_SZ];
    __shared__ float red_s[4][2][32];

    const bool owner = (tid < 32);
    const int ob = tid >> 2;
    const int ou = tid & 3;
    float c_reg = 0.f;

    for (int t = 0; t < T_SZ; t++) {
        float xzr0 = 0.f, xzr1 = 0.f, xzr2 = 0.f, xzr3 = 0.f;
        if (owner) {
            const float* p = xz + ((size_t)(ob * T_SZ + t)) * 2048 + u0 + ou;
            xzr0 = p[0]; xzr1 = p[512]; xzr2 = p[1024]; xzr3 = p[1536];
        }

        if (t > 0) {
            {
                const float4* src = (const float4*)h_out;
                float4* dst = (float4*)h_s;
#pragma unroll
                for (int j = 0; j < 4; j++) {
                    int i4 = tid + j * 256;
                    int b = i4 >> 7, kk4 = i4 & 127;
                    dst[i4] = src[((size_t)b * T_SZ + (t - 1)) * 128 + kk4];
                }
            }
            __syncthreads();

            float A[32];
#pragma unroll
            for (int v = 0; v < 32; v++) A[v] = 0.f;
#pragma unroll
            for (int b = 0; b < 8; b++) {
                const float4* hp4 = (const float4*)(h_s + b * 512 + k0);
                float4 h0 = hp4[0], h1 = hp4[1];
                float hv[8] = {h0.x, h0.y, h0.z, h0.w, h1.x, h1.y, h1.z, h1.w};
#pragma unroll
                for (int g = 0; g < 4; g++)
#pragma unroll
                    for (int kk = 0; kk < 8; kk++)
                        A[b * 4 + g] += hv[kk] * W[g][kk];
            }
#pragma unroll
            for (int o = 16; o >= 1; o >>= 1) {
                const bool hi = (lane & o) != 0;
#pragma unroll
                for (int v = 0; v < 16; v++) {
                    if (v < o) {
                        float lo_v = A[v], hi_v = A[v + o];
                        float send = hi ? lo_v : hi_v;
                        float recv = __shfl_xor_sync(0xffffffffu, send, o);
                        A[v] = (hi ? hi_v : lo_v) + recv;
                    }
                }
            }
            red_s[uu][half][lane] = A[0];
            __syncthreads();
        }

        if (owner) {
            float zi = xzr0, zf = xzr1, zg = xzr2, zo = xzr3;
            if (t > 0) {
                int vb = ob * 4;
                zi += red_s[ou][0][vb + 0] + red_s[ou][1][vb + 0];
                zf += red_s[ou][0][vb + 1] + red_s[ou][1][vb + 1];
                zg += red_s[ou][0][vb + 2] + red_s[ou][1][vb + 2];
                zo += red_s[ou][0][vb + 3] + red_s[ou][1][vb + 3];
            }
            float ig = sigmoidf_(zi);
            float fg = sigmoidf_(zf);
            float gg = tanhf(zg);
            float og = sigmoidf_(zo);
            c_reg = fg * c_reg + ig * gg;
            float hval = og * tanhf(c_reg);
            h_out[((size_t)ob * T_SZ + t) * H_SZ + u0 + ou] = hval;
        }

        if (t < T_SZ - 1) {
            __syncthreads();
            if (tid == 0) {
                asm volatile("red.release.gpu.global.add.u32 [%0], %1;"
                             :: "l"(&g_bar), "r"(1u) : "memory");
                const unsigned target = (unsigned)(t + 1) * 128u;
                unsigned v;
                do {
                    asm volatile("ld.acquire.gpu.global.u32 %0, [%1];"
                                 : "=r"(v) : "l"(&g_bar) : "memory");
                } while (v < target);
            }
            __syncthreads();
        }
    }
}

__global__ void reset_kernel() {
    if (threadIdx.x == 0) g_bar = 0u;
}

// ---------------------------------------------------------------------------
// bf16 split kernels
// ---------------------------------------------------------------------------
__global__ void split_h_kernel(const float* __restrict__ h) {
    size_t id = (size_t)blockIdx.x * 256 + threadIdx.x;   // over 8192*512
    int m = (int)(id >> 9), k = (int)(id & 511);
    float a = h[id];
    __nv_bfloat16 hi = __float2bfloat16(a);
    __nv_bfloat16 lo = __float2bfloat16(a - __bfloat162float(hi));
    g_asp[(size_t)m * 1024 + k]       = hi;
    g_asp[(size_t)m * 1024 + 512 + k] = lo;
}
__global__ void split_w_kernel(const float* __restrict__ rk_W,
                               const float* __restrict__ wk_W,
                               const float* __restrict__ we_W,
                               const float* __restrict__ wa_W)
{
    size_t id = (size_t)blockIdx.x * 256 + threadIdx.x;   // over 7*512*1024
    int mat = (int)(id / (512 * 1024));
    int r2  = (int)(id % (512 * 1024));
    int k = r2 >> 10, n = r2 & 1023;
    const float* W;
    if (mat < 4)       W = rk_W + (size_t)mat * 512 * 1024;
    else if (mat == 4) W = wk_W;
    else if (mat == 5) W = we_W;
    else               W = wa_W;
    float a = W[(size_t)k * 1024 + n];
    __nv_bfloat16 hi = __float2bfloat16(a);
    __nv_bfloat16 lo = __float2bfloat16(a - __bfloat162float(hi));
    __nv_bfloat16* dst = g_bsp + (size_t)mat * 1024 * 1024 + (size_t)n * 1024;
    dst[k]       = hi;
    dst[512 + k] = lo;
}

// ---------------------------------------------------------------------------
// mma.sync bf16-split projection GEMM (proven correct in R12).
// 128x128 tile/CTA, 256 thr = 8 warps (4m x 2n), warp tile 32x64.
// K' = 1536: A'=[Ah,Ah,Al], B'=[Bh,Bl,Bh]; fp32 accumulators.
// ---------------------------------------------------------------------------
#define KC 64
#define NCH 24    // 1536/64
__global__ void __launch_bounds__(256) mma_proj_kernel(
    const float* __restrict__ rk_b, const float* __restrict__ wk_b,
    const float* __restrict__ we_b, const float* __restrict__ wa_b,
    float* __restrict__ rk_out, float* __restrict__ wk_out,
    float* __restrict__ eb_out, float* __restrict__ ab_out)
{
    const int tix = blockIdx.x;            // 7 * 64 * 8
    const int mat = tix >> 9;
    const int rem = tix & 511;
    const int mt  = rem >> 3;
    const int nt  = rem & 7;
    const int m0  = mt * 128;
    const int n0  = nt * 128;

    const __nv_bfloat16* Bmat = g_bsp + (size_t)mat * 1024 * 1024;
    float* C; const float* bias;
    if (mat < 4)       { C = rk_out + (size_t)mat * 8192 * 1024; bias = rk_b + mat * 1024; }
    else if (mat == 4) { C = wk_out; bias = wk_b; }
    else if (mat == 5) { C = eb_out; bias = we_b; }
    else               { C = ab_out; bias = wa_b; }

    __shared__ __align__(128) __nv_bfloat16 As[128 * KC];
    __shared__ __align__(128) __nv_bfloat16 Bs[128 * KC];
    const uint32_t AsU = smem_u32(As);
    const uint32_t BsU = smem_u32(Bs);

    const int tid  = threadIdx.x;
    const int wid  = tid >> 5, lane = tid & 31;
    const int wm   = wid & 3;
    const int wn   = wid >> 2;

    const int lrow = tid >> 1;
    const int lhalf = tid & 1;
    const uint4* A4 = (const uint4*)g_asp;    // row pitch 128 uint4 (2048B)
    const uint4* B4 = (const uint4*)Bmat;

    float d[2][8][4];
#pragma unroll
    for (int i = 0; i < 2; i++)
#pragma unroll
        for (int j = 0; j < 8; j++)
#pragma unroll
            for (int q = 0; q < 4; q++) d[i][j][q] = 0.f;

    uint4 aR[4], bR[4];
#pragma unroll
    for (int i = 0; i < 4; i++) {
        aR[i] = A4[(size_t)(m0 + lrow) * 128 + lhalf * 4 + i];
        bR[i] = B4[(size_t)(n0 + lrow) * 128 + lhalf * 4 + i];
    }

    for (int c = 0; c < NCH; c++) {
#pragma unroll
        for (int i = 0; i < 4; i++) {
            uint32_t off = lrow * 128 + (lhalf * 4 + i) * 16;
            uint32_t sw = SMEM_SWZ(off);
            *(uint4*)((char*)As + sw) = aR[i];
            *(uint4*)((char*)Bs + sw) = bR[i];
        }
        __syncthreads();

        if (c + 1 < NCH) {
            int kb = (c + 1) * KC;
            int acol = (kb < 512) ? kb : kb - 512;      // [Ah,Ah,Al]
            int bcol = (kb < 1024) ? kb : kb - 1024;    // [Bh,Bl,Bh]
#pragma unroll
            for (int i = 0; i < 4; i++) {
                aR[i] = A4[(size_t)(m0 + lrow) * 128 + (acol >> 3) + lhalf * 4 + i];
                bR[i] = B4[(size_t)(n0 + lrow) * 128 + (bcol >> 3) + lhalf * 4 + i];
            }
        }

#pragma unroll
        for (int ksi = 0; ksi < 4; ksi++) {
            uint32_t a0[4], a1[4];
            {
                int row = wm * 32 + (lane & 15);
                uint32_t off = (uint32_t)row * 128 + ksi * 32 + (lane >> 4) * 16;
                uint32_t ad = AsU + SMEM_SWZ(off);
                asm volatile("ldmatrix.sync.aligned.m8n8.x4.shared.b16 {%0,%1,%2,%3}, [%4];"
                             : "=r"(a0[0]), "=r"(a0[1]), "=r"(a0[2]), "=r"(a0[3]) : "r"(ad));
                off = (uint32_t)(row + 16) * 128 + ksi * 32 + (lane >> 4) * 16;
                ad = AsU + SMEM_SWZ(off);
                asm volatile("ldmatrix.sync.aligned.m8n8.x4.shared.b16 {%0,%1,%2,%3}, [%4];"
                             : "=r"(a1[0]), "=r"(a1[1]), "=r"(a1[2]), "=r"(a1[3]) : "r"(ad));
            }
#pragma unroll
            for (int j = 0; j < 8; j++) {
                uint32_t b0[2];
                int brow = wn * 64 + j * 8 + (lane & 7);
                uint32_t off = (uint32_t)brow * 128 + ksi * 32 + ((lane >> 3) & 1) * 16;
                uint32_t bd = BsU + SMEM_SWZ(off);
                asm volatile("ldmatrix.sync.aligned.m8n8.x2.shared.b16 {%0,%1}, [%2];"
                             : "=r"(b0[0]), "=r"(b0[1]) : "r"(bd));
                asm volatile("mma.sync.aligned.m16n8k16.row.col.f32.bf16.bf16.f32 "
                             "{%0,%1,%2,%3}, {%4,%5,%6,%7}, {%8,%9}, {%0,%1,%2,%3};"
                             : "+f"(d[0][j][0]), "+f"(d[0][j][1]),
                               "+f"(d[0][j][2]), "+f"(d[0][j][3])
                             : "r"(a0[0]), "r"(a0[1]), "r"(a0[2]), "r"(a0[3]),
                               "r"(b0[0]), "r"(b0[1]));
                asm volatile("mma.sync.aligned.m16n8k16.row.col.f32.bf16.bf16.f32 "
                             "{%0,%1,%2,%3}, {%4,%5,%6,%7}, {%8,%9}, {%0,%1,%2,%3};"
                             : "+f"(d[1][j][0]), "+f"(d[1][j][1]),
                               "+f"(d[1][j][2]), "+f"(d[1][j][3])
                             : "r"(a1[0]), "r"(a1[1]), "r"(a1[2]), "r"(a1[3]),
                               "r"(b0[0]), "r"(b0[1]));
            }
        }
        __syncthreads();
    }

    const int r0 = lane >> 2;
    const int c0 = (lane & 3) * 2;
#pragma unroll
    for (int i = 0; i < 2; i++) {
#pragma unroll
        for (int j = 0; j < 8; j++) {
            int col = n0 + wn * 64 + j * 8 + c0;
            float b0v = bias[col], b1v = bias[col + 1];
            int rowA = m0 + wm * 32 + i * 16 + r0;
            float2 v0 = make_float2(d[i][j][0] + b0v, d[i][j][1] + b1v);
            float2 v1 = make_float2(d[i][j][2] + b0v, d[i][j][3] + b1v);
            *(float2*)&C[(size_t)rowA * 1024 + col]       = v0;
            *(float2*)&C[(size_t)(rowA + 8) * 1024 + col] = v1;
        }
    }
}

// ---------------------------------------------------------------------------
// memory row inverse-norms and column sums
// ---------------------------------------------------------------------------
__global__ void rownorm_kernel(const float* __restrict__ mem) {
    int t = blockIdx.x;
    float4 v = ((const float4*)(mem + (size_t)t * M_SZ))[threadIdx.x];
    float ss = v.x * v.x + v.y * v.y + v.z * v.z + v.w * v.w;
    ss = blockReduceSum(ss);
    if (threadIdx.x == 0) g_invn[t] = rsqrtf(fmaxf(ss, 1e-12f));
}
__global__ void colsum_kernel(const float* __restrict__ mem) {
    int j = blockIdx.x * 256 + threadIdx.x;
    float s = 0.f;
    for (int i = 0; i < M_SZ; i++) s += mem[(size_t)i * M_SZ + j];
    g_colsum[j] = s;
}

// ---------------------------------------------------------------------------
// sim / softmax / memupd (unchanged)
// ---------------------------------------------------------------------------
__global__ void sim_kernel(const float* __restrict__ logits,
                           const float* __restrict__ mem,
                           float* __restrict__ simout)
{
    int row = blockIdx.x;
    int t = row & (T_SZ - 1);
    float4 xv = ((const float4*)(logits + (size_t)row * M_SZ))[threadIdx.x];
    float m = fmaxf(fmaxf(xv.x, xv.y), fmaxf(xv.z, xv.w));
    m = blockReduceMax(m);
    float e0 = __expf(xv.x - m), e1 = __expf(xv.y - m);
    float e2 = __expf(xv.z - m), e3 = __expf(xv.w - m);
    float4 mv = ((const float4*)(mem + (size_t)t * M_SZ))[threadIdx.x];
    float se2 = e0 * e0 + e1 * e1 + e2 * e2 + e3 * e3;
    float sd  = e0 * mv.x + e1 * mv.y + e2 * mv.z + e3 * mv.w;
    se2 = blockReduceSum(se2);
    sd  = blockReduceSum(sd);
    if (threadIdx.x == 0)
        simout[row] = -sd * g_invn[t] * rsqrtf(fmaxf(se2, 1e-12f));
}
__global__ void softmax_row_kernel(const float* __restrict__ in,
                                   const float* __restrict__ scale,
                                   float* __restrict__ out)
{
    int r = blockIdx.x;
    float4 xv = ((const float4*)(in + (size_t)r * 1024))[threadIdx.x];
    float m = fmaxf(fmaxf(xv.x, xv.y), fmaxf(xv.z, xv.w));
    m = blockReduceMax(m);
    float e0 = __expf(xv.x - m), e1 = __expf(xv.y - m);
    float e2 = __expf(xv.z - m), e3 = __expf(xv.w - m);
    float S = blockReduceSum(e0 + e1 + e2 + e3);
    float inv = 1.f / S;
    float4 o = make_float4(e0 * inv, e1 * inv, e2 * inv, e3 * inv);
    if (scale) {
        float4 cs = ((const float4*)scale)[threadIdx.x];
        o.x *= cs.x; o.y *= cs.y; o.z *= cs.z; o.w *= cs.w;
    }
    ((float4*)(out + (size_t)r * 1024))[threadIdx.x] = o;
}
__global__ void memupd_kernel(const float* __restrict__ eb,
                              const float* __restrict__ ab,
                              const float* __restrict__ mem,
                              float* __restrict__ out)
{
    size_t idx = (size_t)blockIdx.x * blockDim.x + threadIdx.x;
    size_t flat = idx * 4;
    int b   = (int)(flat >> 20);
    int rem = (int)(flat & 0xFFFFFu);
    int i = rem >> 10;
    int j = rem & 1023;
    float4 e = ((const float4*)eb)[idx];
    float4 a = ((const float4*)ab)[idx];
    float4 m = *(const float4*)(mem + (size_t)i * M_SZ + j);
    float4 w = *(const float4*)(g_ww + b * 1024 + j);
    float4 o;
    o.x = (1.f - w.x * sigmoidf_(e.x)) * m.x + w.x * a.x;
    o.y = (1.f - w.y * sigmoidf_(e.y)) * m.y + w.y * a.y;
    o.z = (1.f - w.z * sigmoidf_(e.z)) * m.z + w.z * a.z;
    o.w = (1.f - w.w * sigmoidf_(e.w)) * m.w + w.w * a.w;
    ((float4*)out)[idx] = o;
}

// ---------------------------------------------------------------------------
// Launch
// ---------------------------------------------------------------------------
extern "C" void kernel_launch(void* const* d_in, const int* in_sizes, int n_in,
                              void* d_out, int out_size)
{
    (void)in_sizes; (void)n_in; (void)out_size;
    const float* inputs = (const float*)d_in[0];
    const float* memory = (const float*)d_in[1];
    const float* Wx     = (const float*)d_in[2];
    const float* Wh     = (const float*)d_in[3];
    const float* bvec   = (const float*)d_in[4];
    const float* rk_W   = (const float*)d_in[5];
    const float* rk_b   = (const float*)d_in[6];
    const float* wk_W   = (const float*)d_in[7];
    const float* wk_b   = (const float*)d_in[8];
    const float* we_W   = (const float*)d_in[9];
    const float* we_b   = (const float*)d_in[10];
    const float* wa_W   = (const float*)d_in[11];
    const float* wa_b   = (const float*)d_in[12];
    float* out = (float*)d_out;

    float *xz, *h, *rk, *wk, *eb, *ab, *sim, *simw, *ww, *colsum;
    cudaGetSymbolAddress((void**)&xz,   g_xz);
    cudaGetSymbolAddress((void**)&h,    g_h);
    cudaGetSymbolAddress((void**)&rk,   g_rk);
    cudaGetSymbolAddress((void**)&wk,   g_wk);
    cudaGetSymbolAddress((void**)&eb,   g_eb);
    cudaGetSymbolAddress((void**)&ab,   g_ab);
    cudaGetSymbolAddress((void**)&sim,  g_sim);
    cudaGetSymbolAddress((void**)&simw, g_simw);
    cudaGetSymbolAddress((void**)&ww,   g_ww);
    cudaGetSymbolAddress((void**)&colsum, g_colsum);

    const int MROWS = B_SZ * T_SZ; // 8192

    reset_kernel<<<1, 32>>>();
    rownorm_kernel<<<M_SZ, 256>>>(memory);
    colsum_kernel<<<M_SZ / 256, 256>>>(memory);

    // weight splits (independent of h)
    split_w_kernel<<<7 * 512 * 1024 / 256, 256>>>(rk_W, wk_W, we_W, wa_W);

    // xz = inputs @ Wx + b  (fp32 FFMA)
    sgemm_kernel<<<dim3(2048 / 128, MROWS / 128), 256>>>(
        inputs, Wx, bvec, xz, 2048, 256);

    // LSTM scan -> h  (128 CTAs x 256 threads, R5-proven)
    lstm_kernel<<<128, 256>>>(xz, Wh, h);

    // split h into bf16 hi/lo
    split_h_kernel<<<MROWS * H_SZ / 256, 256>>>(h);

    // all 7 projection GEMMs via mma.sync bf16 split
    mma_proj_kernel<<<7 * 512, 256>>>(rk_b, wk_b, we_b, wa_b, rk, wk, eb, ab);

    // similarity reductions
    sim_kernel<<<R_SZ * B_SZ * T_SZ, 256>>>(rk, memory, sim);
    sim_kernel<<<B_SZ * T_SZ, 256>>>(wk, memory, simw);

    // reads -> out[0:32768)
    softmax_row_kernel<<<R_SZ * B_SZ, 256>>>(sim, colsum, out);
    softmax_row_kernel<<<B_SZ, 256>>>(simw, (const float*)nullptr, ww);

    // new_memory -> out[32768 : ]
    memupd_kernel<<<(B_SZ * M_SZ * M_SZ / 4) / 256, 256>>>(
        eb, ab, memory, out + R_SZ * B_SZ * T_SZ);
}

// round 16
// speedup vs baseline: 1.2232x; 1.0459x over previous
#include <cuda_runtime.h>
#include <cuda_bf16.h>
#include <cstdint>
#include <cstddef>

#define B_SZ 8
#define T_SZ 1024
#define D_SZ 256
#define H_SZ 512
#define M_SZ 1024
#define R_SZ 4

// ---------------------------------------------------------------------------
// Scratch (static device globals -- no runtime allocation allowed)
// ---------------------------------------------------------------------------
__device__ float g_xz[(size_t)B_SZ * T_SZ * 4 * H_SZ];   // 64 MB
__device__ float g_h [(size_t)B_SZ * T_SZ * H_SZ];       // 16 MB
__device__ float g_rk[(size_t)R_SZ * B_SZ * T_SZ * M_SZ];// 128 MB
__device__ float g_wk[(size_t)B_SZ * T_SZ * M_SZ];       // 32 MB
__device__ float g_eb[(size_t)B_SZ * T_SZ * M_SZ];       // 32 MB
__device__ float g_ab[(size_t)B_SZ * T_SZ * M_SZ];       // 32 MB
__device__ float g_sim [R_SZ * B_SZ * T_SZ];
__device__ float g_simw[B_SZ * T_SZ];
__device__ float g_ww  [B_SZ * T_SZ];
__device__ float g_invn[M_SZ];
__device__ float g_colsum[M_SZ];
__device__ unsigned g_bar;
// bf16-split operands: A' = [hi(h) | lo(h)]  (8192 x 1024 bf16)
__device__ __nv_bfloat16 g_asp[(size_t)B_SZ * T_SZ * 2 * H_SZ];
// B' = per-matrix transposed [hi(W^T) | lo(W^T)]  (7 x 1024 x 1024 bf16)
__device__ __nv_bfloat16 g_bsp[(size_t)7 * M_SZ * 2 * H_SZ];

#define SMEM_SWZ64(off) ((off) ^ (((off) >> 3) & 0x30))

__device__ __forceinline__ uint32_t smem_u32(const void* p) {
    uint32_t a;
    asm("{ .reg .u64 t; cvta.to.shared.u64 t, %1; cvt.u32.u64 %0, t; }"
        : "=r"(a) : "l"(p));
    return a;
}

// ---------------------------------------------------------------------------
// Block-wide reductions (blockDim.x == 256)
// ---------------------------------------------------------------------------
__device__ __forceinline__ float blockReduceSum(float v) {
    __shared__ float sh[8];
    int lane = threadIdx.x & 31, w = threadIdx.x >> 5;
#pragma unroll
    for (int o = 16; o; o >>= 1) v += __shfl_xor_sync(0xffffffffu, v, o);
    if (lane == 0) sh[w] = v;
    __syncthreads();
    if (w == 0) {
        float x = (lane < 8) ? sh[lane] : 0.f;
#pragma unroll
        for (int o = 4; o; o >>= 1) x += __shfl_xor_sync(0xffffffffu, x, o);
        if (lane == 0) sh[0] = x;
    }
    __syncthreads();
    float r = sh[0];
    __syncthreads();
    return r;
}
__device__ __forceinline__ float blockReduceMax(float v) {
    __shared__ float sh[8];
    int lane = threadIdx.x & 31, w = threadIdx.x >> 5;
#pragma unroll
    for (int o = 16; o; o >>= 1) v = fmaxf(v, __shfl_xor_sync(0xffffffffu, v, o));
    if (lane == 0) sh[w] = v;
    __syncthreads();
    if (w == 0) {
        float x = (lane < 8) ? sh[lane] : -3.402823466e38f;
#pragma unroll
        for (int o = 4; o; o >>= 1) x = fmaxf(x, __shfl_xor_sync(0xffffffffu, x, o));
        if (lane == 0) sh[0] = x;
    }
    __syncthreads();
    float r = sh[0];
    __syncthreads();
    return r;
}
__device__ __forceinline__ float sigmoidf_(float x) {
    return 1.f / (1.f + __expf(-x));
}

// ---------------------------------------------------------------------------
// fp32 SGEMM (xz = inputs @ Wx + b; proven)
// ---------------------------------------------------------------------------
__global__ void __launch_bounds__(256) sgemm_kernel(
    const float* __restrict__ A, const float* __restrict__ B,
    const float* __restrict__ bias, float* __restrict__ C, int N, int K)
{
    const int n0 = blockIdx.x * 128;
    const int m0 = blockIdx.y * 128;
    __shared__ float As[8][128];
    __shared__ float Bs[8][128];
    const int tid  = threadIdx.x;
    const int arow = tid >> 1, ak = (tid & 1) * 4;
    const int bk   = tid >> 5, bc = (tid & 31) * 4;
    const int tx   = tid & 15, ty = tid >> 4;
    const float* Ap = A + (size_t)(m0 + arow) * K + ak;
    const float* Bp = B + (size_t)bk * N + n0 + bc;
    float4 aR = *(const float4*)Ap;
    float4 bR = *(const float4*)Bp;
    float acc[8][8];
#pragma unroll
    for (int i = 0; i < 8; i++)
#pragma unroll
        for (int j = 0; j < 8; j++) acc[i][j] = 0.f;
    const int KT = K >> 3;
    for (int kt = 0; kt < KT; kt++) {
        As[ak + 0][arow] = aR.x; As[ak + 1][arow] = aR.y;
        As[ak + 2][arow] = aR.z; As[ak + 3][arow] = aR.w;
        *(float4*)&Bs[bk][bc] = bR;
        __syncthreads();
        if (kt + 1 < KT) {
            aR = *(const float4*)(Ap + (kt + 1) * 8);
            bR = *(const float4*)(Bp + (size_t)(kt + 1) * 8 * N);
        }
#pragma unroll
        for (int kk = 0; kk < 8; kk++) {
            float4 a0 = *(const float4*)&As[kk][ty * 4];
            float4 a1 = *(const float4*)&As[kk][64 + ty * 4];
            float4 b0 = *(const float4*)&Bs[kk][tx * 4];
            float4 b1 = *(const float4*)&Bs[kk][64 + tx * 4];
            float ar[8] = {a0.x, a0.y, a0.z, a0.w, a1.x, a1.y, a1.z, a1.w};
            float br[8] = {b0.x, b0.y, b0.z, b0.w, b1.x, b1.y, b1.z, b1.w};
#pragma unroll
            for (int i = 0; i < 8; i++)
#pragma unroll
                for (int j = 0; j < 8; j++) acc[i][j] += ar[i] * br[j];
        }
        __syncthreads();
    }
    float4 bias0 = *(const float4*)&bias[n0 + tx * 4];
    float4 bias1 = *(const float4*)&bias[n0 + 64 + tx * 4];
    float bb[8] = {bias0.x, bias0.y, bias0.z, bias0.w,
                   bias1.x, bias1.y, bias1.z, bias1.w};
#pragma unroll
    for (int i = 0; i < 8; i++) {
        int row = m0 + ((i < 4) ? (ty * 4 + i) : (64 + ty * 4 + (i - 4)));
        float4 o0 = make_float4(acc[i][0] + bb[0], acc[i][1] + bb[1],
                                acc[i][2] + bb[2], acc[i][3] + bb[3]);
        float4 o1 = make_float4(acc[i][4] + bb[4], acc[i][5] + bb[5],
                                acc[i][6] + bb[6], acc[i][7] + bb[7]);
        *(float4*)&C[(size_t)row * N + n0 + tx * 4]      = o0;
        *(float4*)&C[(size_t)row * N + n0 + 64 + tx * 4] = o1;
    }
}

// ---------------------------------------------------------------------------
// Persistent LSTM (R5, 128 CTAs x 256 threads — proven; DO NOT TOUCH)
// ---------------------------------------------------------------------------
__global__ void __launch_bounds__(256, 1) lstm_kernel(
    const float* __restrict__ xz, const float* __restrict__ Wh,
    float* __restrict__ h_out)
{
    const int cb = blockIdx.x;
    const int u0 = cb * 4;
    const int tid = threadIdx.x;
    const int uu = tid >> 6;
    const int ks = tid & 63;
    const int k0 = ks * 8;
    const int lane = tid & 31;
    const int half = (tid >> 5) & 1;

    float W[4][8];
#pragma unroll
    for (int g = 0; g < 4; g++)
#pragma unroll
        for (int kk = 0; kk < 8; kk++)
            W[g][kk] = Wh[(size_t)(k0 + kk) * 2048 + g * 512 + u0 + uu];

    __shared__ float h_s[B_SZ * H_SZ];
    __shared__ float red_s[4][2][32];

    const bool owner = (tid < 32);
    const int ob = tid >> 2;
    const int ou = tid & 3;
    float c_reg = 0.f;

    for (int t = 0; t < T_SZ; t++) {
        float xzr0 = 0.f, xzr1 = 0.f, xzr2 = 0.f, xzr3 = 0.f;
        if (owner) {
            const float* p = xz + ((size_t)(ob * T_SZ + t)) * 2048 + u0 + ou;
            xzr0 = p[0]; xzr1 = p[512]; xzr2 = p[1024]; xzr3 = p[1536];
        }

        if (t > 0) {
            {
                const float4* src = (const float4*)h_out;
                float4* dst = (float4*)h_s;
#pragma unroll
                for (int j = 0; j < 4; j++) {
                    int i4 = tid + j * 256;
                    int b = i4 >> 7, kk4 = i4 & 127;
                    dst[i4] = src[((size_t)b * T_SZ + (t - 1)) * 128 + kk4];
                }
            }
            __syncthreads();

            float A[32];
#pragma unroll
            for (int v = 0; v < 32; v++) A[v] = 0.f;
#pragma unroll
            for (int b = 0; b < 8; b++) {
                const float4* hp4 = (const float4*)(h_s + b * 512 + k0);
                float4 h0 = hp4[0], h1 = hp4[1];
                float hv[8] = {h0.x, h0.y, h0.z, h0.w, h1.x, h1.y, h1.z, h1.w};
#pragma unroll
                for (int g = 0; g < 4; g++)
#pragma unroll
                    for (int kk = 0; kk < 8; kk++)
                        A[b * 4 + g] += hv[kk] * W[g][kk];
            }
#pragma unroll
            for (int o = 16; o >= 1; o >>= 1) {
                const bool hi = (lane & o) != 0;
#pragma unroll
                for (int v = 0; v < 16; v++) {
                    if (v < o) {
                        float lo_v = A[v], hi_v = A[v + o];
                        float send = hi ? lo_v : hi_v;
                        float recv = __shfl_xor_sync(0xffffffffu, send, o);
                        A[v] = (hi ? hi_v : lo_v) + recv;
                    }
                }
            }
            red_s[uu][half][lane] = A[0];
            __syncthreads();
        }

        if (owner) {
            float zi = xzr0, zf = xzr1, zg = xzr2, zo = xzr3;
            if (t > 0) {
                int vb = ob * 4;
                zi += red_s[ou][0][vb + 0] + red_s[ou][1][vb + 0];
                zf += red_s[ou][0][vb + 1] + red_s[ou][1][vb + 1];
                zg += red_s[ou][0][vb + 2] + red_s[ou][1][vb + 2];
                zo += red_s[ou][0][vb + 3] + red_s[ou][1][vb + 3];
            }
            float ig = sigmoidf_(zi);
            float fg = sigmoidf_(zf);
            float gg = tanhf(zg);
            float og = sigmoidf_(zo);
            c_reg = fg * c_reg + ig * gg;
            float hval = og * tanhf(c_reg);
            h_out[((size_t)ob * T_SZ + t) * H_SZ + u0 + ou] = hval;
        }

        if (t < T_SZ - 1) {
            __syncthreads();
            if (tid == 0) {
                asm volatile("red.release.gpu.global.add.u32 [%0], %1;"
                             :: "l"(&g_bar), "r"(1u) : "memory");
                const unsigned target = (unsigned)(t + 1) * 128u;
                unsigned v;
                do {
                    asm volatile("ld.acquire.gpu.global.u32 %0, [%1];"
                                 : "=r"(v) : "l"(&g_bar) : "memory");
                } while (v < target);
            }
            __syncthreads();
        }
    }
}

__global__ void reset_kernel() {
    if (threadIdx.x == 0) g_bar = 0u;
}

// ---------------------------------------------------------------------------
// bf16 split kernels
// ---------------------------------------------------------------------------
__global__ void split_h_kernel(const float* __restrict__ h) {
    size_t id = (size_t)blockIdx.x * 256 + threadIdx.x;   // over 8192*512
    int m = (int)(id >> 9), k = (int)(id & 511);
    float a = h[id];
    __nv_bfloat16 hi = __float2bfloat16(a);
    __nv_bfloat16 lo = __float2bfloat16(a - __bfloat162float(hi));
    g_asp[(size_t)m * 1024 + k]       = hi;
    g_asp[(size_t)m * 1024 + 512 + k] = lo;
}
// Tiled transpose-split: 64(k) x 64(n) tile per CTA; coalesced both sides.
// grid: 7 mats x 8 ktiles x 16 ntiles = 896
__global__ void __launch_bounds__(256) split_w_kernel(
    const float* __restrict__ rk_W, const float* __restrict__ wk_W,
    const float* __restrict__ we_W, const float* __restrict__ wa_W)
{
    const int bx = blockIdx.x;
    const int mat = bx >> 7;            // /128
    const int rem = bx & 127;
    const int kt  = rem >> 4;           // 0..7
    const int ntl = rem & 15;           // 0..15
    const int k0 = kt * 64, n0 = ntl * 64;

    const float* W;
    if (mat < 4)       W = rk_W + (size_t)mat * 512 * 1024;
    else if (mat == 4) W = wk_W;
    else if (mat == 5) W = we_W;
    else               W = wa_W;
    __nv_bfloat16* dst = g_bsp + (size_t)mat * 1024 * 1024;

    __shared__ float s[64 * 65];
    const int tid = threadIdx.x;
#pragma unroll
    for (int p = 0; p < 16; p++) {
        int idx = p * 256 + tid;
        int kk = idx >> 6, nn = idx & 63;
        s[kk * 65 + nn] = W[(size_t)(k0 + kk) * 1024 + n0 + nn];
    }
    __syncthreads();
#pragma unroll
    for (int p = 0; p < 16; p++) {
        int idx = p * 256 + tid;
        int nn = idx >> 6, kk = idx & 63;
        float a = s[kk * 65 + nn];
        __nv_bfloat16 hi = __float2bfloat16(a);
        __nv_bfloat16 lo = __float2bfloat16(a - __bfloat162float(hi));
        __nv_bfloat16* row = dst + (size_t)(n0 + nn) * 1024;
        row[k0 + kk]       = hi;
        row[512 + k0 + kk] = lo;
    }
}

// ---------------------------------------------------------------------------
// mma.sync bf16-split projection GEMM — DOUBLE-BUFFERED (KC=32, SW64 rows).
// 128x128 tile/CTA, 256 thr = 8 warps (4m x 2n), warp tile 32x64.
// K' = 1536: A'=[Ah,Ah,Al], B'=[Bh,Bl,Bh]; fp32 accumulators.
// ---------------------------------------------------------------------------
#define KC 32
#define NCH 48    // 1536/32
__global__ void __launch_bounds__(256) mma_proj_kernel(
    const float* __restrict__ rk_b, const float* __restrict__ wk_b,
    const float* __restrict__ we_b, const float* __restrict__ wa_b,
    float* __restrict__ rk_out, float* __restrict__ wk_out,
    float* __restrict__ eb_out, float* __restrict__ ab_out)
{
    const int tix = blockIdx.x;            // 7 * 64 * 8
    const int mat = tix >> 9;
    const int rem = tix & 511;
    const int mt  = rem >> 3;
    const int nt  = rem & 7;
    const int m0  = mt * 128;
    const int n0  = nt * 128;

    const __nv_bfloat16* Bmat = g_bsp + (size_t)mat * 1024 * 1024;
    float* C; const float* bias;
    if (mat < 4)       { C = rk_out + (size_t)mat * 8192 * 1024; bias = rk_b + mat * 1024; }
    else if (mat == 4) { C = wk_out; bias = wk_b; }
    else if (mat == 5) { C = eb_out; bias = we_b; }
    else               { C = ab_out; bias = wa_b; }

    // 2 stages x (128 rows x 32 cols bf16 = 8KB) per operand = 32KB total
    __shared__ __align__(128) __nv_bfloat16 As[2][128 * KC];
    __shared__ __align__(128) __nv_bfloat16 Bs[2][128 * KC];
    const uint32_t AsU[2] = {smem_u32(As[0]), smem_u32(As[1])};
    const uint32_t BsU[2] = {smem_u32(Bs[0]), smem_u32(Bs[1])};

    const int tid  = threadIdx.x;
    const int wid  = tid >> 5, lane = tid & 31;
    const int wm   = wid & 3;
    const int wn   = wid >> 2;

    // gmem load map: row = tid>>1 (0..127), half = tid&1 -> 2 uint4 (32B)
    const int lrow = tid >> 1;
    const int lh   = tid & 1;
    const uint4* A4 = (const uint4*)g_asp;    // row pitch 128 uint4 (2048B)
    const uint4* B4 = (const uint4*)Bmat;

    float d[2][8][4];
#pragma unroll
    for (int i = 0; i < 2; i++)
#pragma unroll
        for (int j = 0; j < 8; j++)
#pragma unroll
            for (int q = 0; q < 4; q++) d[i][j][q] = 0.f;

    uint4 aR[2], bR[2];
    // chunk 0 (acol = bcol = 0)
#pragma unroll
    for (int i = 0; i < 2; i++) {
        aR[i] = A4[(size_t)(m0 + lrow) * 128 + lh * 2 + i];
        bR[i] = B4[(size_t)(n0 + lrow) * 128 + lh * 2 + i];
    }
#pragma unroll
    for (int i = 0; i < 2; i++) {
        uint32_t off = lrow * 64 + (lh * 2 + i) * 16;
        uint32_t sw = SMEM_SWZ64(off);
        *(uint4*)((char*)As[0] + sw) = aR[i];
        *(uint4*)((char*)Bs[0] + sw) = bR[i];
    }
    __syncthreads();

    for (int c = 0; c < NCH; c++) {
        const int buf = c & 1;
        // prefetch next chunk FIRST (hide gmem latency under mma)
        if (c + 1 < NCH) {
            int kb = (c + 1) * KC;
            int acol = (kb < 512) ? kb : kb - 512;      // [Ah,Ah,Al]
            int bcol = (kb < 1024) ? kb : kb - 1024;    // [Bh,Bl,Bh]
#pragma unroll
            for (int i = 0; i < 2; i++) {
                aR[i] = A4[(size_t)(m0 + lrow) * 128 + (acol >> 3) + lh * 2 + i];
                bR[i] = B4[(size_t)(n0 + lrow) * 128 + (bcol >> 3) + lh * 2 + i];
            }
        }

        // compute on buf: 2 k16 steps
#pragma unroll
        for (int ksi = 0; ksi < 2; ksi++) {
            uint32_t a0[4], a1[4];
            {
                int row = wm * 32 + (lane & 15);
                uint32_t off = (uint32_t)row * 64 + ksi * 32 + (lane >> 4) * 16;
                uint32_t ad = AsU[buf] + SMEM_SWZ64(off);
                asm volatile("ldmatrix.sync.aligned.m8n8.x4.shared.b16 {%0,%1,%2,%3}, [%4];"
                             : "=r"(a0[0]), "=r"(a0[1]), "=r"(a0[2]), "=r"(a0[3]) : "r"(ad));
                off = (uint32_t)(row + 16) * 64 + ksi * 32 + (lane >> 4) * 16;
                ad = AsU[buf] + SMEM_SWZ64(off);
                asm volatile("ldmatrix.sync.aligned.m8n8.x4.shared.b16 {%0,%1,%2,%3}, [%4];"
                             : "=r"(a1[0]), "=r"(a1[1]), "=r"(a1[2]), "=r"(a1[3]) : "r"(ad));
            }
#pragma unroll
            for (int j = 0; j < 8; j++) {
                uint32_t b0[2];
                int brow = wn * 64 + j * 8 + (lane & 7);
                uint32_t off = (uint32_t)brow * 64 + ksi * 32 + ((lane >> 3) & 1) * 16;
                uint32_t bd = BsU[buf] + SMEM_SWZ64(off);
                asm volatile("ldmatrix.sync.aligned.m8n8.x2.shared.b16 {%0,%1}, [%2];"
                             : "=r"(b0[0]), "=r"(b0[1]) : "r"(bd));
                asm volatile("mma.sync.aligned.m16n8k16.row.col.f32.bf16.bf16.f32 "
                             "{%0,%1,%2,%3}, {%4,%5,%6,%7}, {%8,%9}, {%0,%1,%2,%3};"
                             : "+f"(d[0][j][0]), "+f"(d[0][j][1]),
                               "+f"(d[0][j][2]), "+f"(d[0][j][3])
                             : "r"(a0[0]), "r"(a0[1]), "r"(a0[2]), "r"(a0[3]),
                               "r"(b0[0]), "r"(b0[1]));
                asm volatile("mma.sync.aligned.m16n8k16.row.col.f32.bf16.bf16.f32 "
                             "{%0,%1,%2,%3}, {%4,%5,%6,%7}, {%8,%9}, {%0,%1,%2,%3};"
                             : "+f"(d[1][j][0]), "+f"(d[1][j][1]),
                               "+f"(d[1][j][2]), "+f"(d[1][j][3])
                             : "r"(a1[0]), "r"(a1[1]), "r"(a1[2]), "r"(a1[3]),
                               "r"(b0[0]), "r"(b0[1]));
            }
        }

        // store prefetched chunk into the OTHER buffer (no WAR with compute;
        // the sync at end of the previous iteration ordered its readers)
        if (c + 1 < NCH) {
            const int nb = buf ^ 1;
#pragma unroll
            for (int i = 0; i < 2; i++) {
                uint32_t off = lrow * 64 + (lh * 2 + i) * 16;
                uint32_t sw = SMEM_SWZ64(off);
                *(uint4*)((char*)As[nb] + sw) = aR[i];
                *(uint4*)((char*)Bs[nb] + sw) = bR[i];
            }
            __syncthreads();
        }
    }

    const int r0 = lane >> 2;
    const int c0 = (lane & 3) * 2;
#pragma unroll
    for (int i = 0; i < 2; i++) {
#pragma unroll
        for (int j = 0; j < 8; j++) {
            int col = n0 + wn * 64 + j * 8 + c0;
            float b0v = bias[col], b1v = bias[col + 1];
            int rowA = m0 + wm * 32 + i * 16 + r0;
            float2 v0 = make_float2(d[i][j][0] + b0v, d[i][j][1] + b1v);
            float2 v1 = make_float2(d[i][j][2] + b0v, d[i][j][3] + b1v);
            *(float2*)&C[(size_t)rowA * 1024 + col]       = v0;
            *(float2*)&C[(size_t)(rowA + 8) * 1024 + col] = v1;
        }
    }
}

// ---------------------------------------------------------------------------
// memory row inverse-norms and column sums
// ---------------------------------------------------------------------------
__global__ void rownorm_kernel(const float* __restrict__ mem) {
    int t = blockIdx.x;
    float4 v = ((const float4*)(mem + (size_t)t * M_SZ))[threadIdx.x];
    float ss = v.x * v.x + v.y * v.y + v.z * v.z + v.w * v.w;
    ss = blockReduceSum(ss);
    if (threadIdx.x == 0) g_invn[t] = rsqrtf(fmaxf(ss, 1e-12f));
}
__global__ void colsum_kernel(const float* __restrict__ mem) {
    int j = blockIdx.x * 256 + threadIdx.x;
    float s = 0.f;
    for (int i = 0; i < M_SZ; i++) s += mem[(size_t)i * M_SZ + j];
    g_colsum[j] = s;
}

// ---------------------------------------------------------------------------
// sim / softmax / memupd (unchanged)
// ---------------------------------------------------------------------------
__global__ void sim_kernel(const float* __restrict__ logits,
                           const float* __restrict__ mem,
                           float* __restrict__ simout)
{
    int row = blockIdx.x;
    int t = row & (T_SZ - 1);
    float4 xv = ((const float4*)(logits + (size_t)row * M_SZ))[threadIdx.x];
    float m = fmaxf(fmaxf(xv.x, xv.y), fmaxf(xv.z, xv.w));
    m = blockReduceMax(m);
    float e0 = __expf(xv.x - m), e1 = __expf(xv.y - m);
    float e2 = __expf(xv.z - m), e3 = __expf(xv.w - m);
    float4 mv = ((const float4*)(mem + (size_t)t * M_SZ))[threadIdx.x];
    float se2 = e0 * e0 + e1 * e1 + e2 * e2 + e3 * e3;
    float sd  = e0 * mv.x + e1 * mv.y + e2 * mv.z + e3 * mv.w;
    se2 = blockReduceSum(se2);
    sd  = blockReduceSum(sd);
    if (threadIdx.x == 0)
        simout[row] = -sd * g_invn[t] * rsqrtf(fmaxf(se2, 1e-12f));
}
__global__ void softmax_row_kernel(const float* __restrict__ in,
                                   const float* __restrict__ scale,
                                   float* __restrict__ out)
{
    int r = blockIdx.x;
    float4 xv = ((const float4*)(in + (size_t)r * 1024))[threadIdx.x];
    float m = fmaxf(fmaxf(xv.x, xv.y), fmaxf(xv.z, xv.w));
    m = blockReduceMax(m);
    float e0 = __expf(xv.x - m), e1 = __expf(xv.y - m);
    float e2 = __expf(xv.z - m), e3 = __expf(xv.w - m);
    float S = blockReduceSum(e0 + e1 + e2 + e3);
    float inv = 1.f / S;
    float4 o = make_float4(e0 * inv, e1 * inv, e2 * inv, e3 * inv);
    if (scale) {
        float4 cs = ((const float4*)scale)[threadIdx.x];
        o.x *= cs.x; o.y *= cs.y; o.z *= cs.z; o.w *= cs.w;
    }
    ((float4*)(out + (size_t)r * 1024))[threadIdx.x] = o;
}
__global__ void memupd_kernel(const float* __restrict__ eb,
                              const float* __restrict__ ab,
                              const float* __restrict__ mem,
                              float* __restrict__ out)
{
    size_t idx = (size_t)blockIdx.x * blockDim.x + threadIdx.x;
    size_t flat = idx * 4;
    int b   = (int)(flat >> 20);
    int rem = (int)(flat & 0xFFFFFu);
    int i = rem >> 10;
    int j = rem & 1023;
    float4 e = ((const float4*)eb)[idx];
    float4 a = ((const float4*)ab)[idx];
    float4 m = *(const float4*)(mem + (size_t)i * M_SZ + j);
    float4 w = *(const float4*)(g_ww + b * 1024 + j);
    float4 o;
    o.x = (1.f - w.x * sigmoidf_(e.x)) * m.x + w.x * a.x;
    o.y = (1.f - w.y * sigmoidf_(e.y)) * m.y + w.y * a.y;
    o.z = (1.f - w.z * sigmoidf_(e.z)) * m.z + w.z * a.z;
    o.w = (1.f - w.w * sigmoidf_(e.w)) * m.w + w.w * a.w;
    ((float4*)out)[idx] = o;
}

// ---------------------------------------------------------------------------
// Launch
// ---------------------------------------------------------------------------
extern "C" void kernel_launch(void* const* d_in, const int* in_sizes, int n_in,
                              void* d_out, int out_size)
{
    (void)in_sizes; (void)n_in; (void)out_size;
    const float* inputs = (const float*)d_in[0];
    const float* memory = (const float*)d_in[1];
    const float* Wx     = (const float*)d_in[2];
    const float* Wh     = (const float*)d_in[3];
    const float* bvec   = (const float*)d_in[4];
    const float* rk_W   = (const float*)d_in[5];
    const float* rk_b   = (const float*)d_in[6];
    const float* wk_W   = (const float*)d_in[7];
    const float* wk_b   = (const float*)d_in[8];
    const float* we_W   = (const float*)d_in[9];
    const float* we_b   = (const float*)d_in[10];
    const float* wa_W   = (const float*)d_in[11];
    const float* wa_b   = (const float*)d_in[12];
    float* out = (float*)d_out;

    float *xz, *h, *rk, *wk, *eb, *ab, *sim, *simw, *ww, *colsum;
    cudaGetSymbolAddress((void**)&xz,   g_xz);
    cudaGetSymbolAddress((void**)&h,    g_h);
    cudaGetSymbolAddress((void**)&rk,   g_rk);
    cudaGetSymbolAddress((void**)&wk,   g_wk);
    cudaGetSymbolAddress((void**)&eb,   g_eb);
    cudaGetSymbolAddress((void**)&ab,   g_ab);
    cudaGetSymbolAddress((void**)&sim,  g_sim);
    cudaGetSymbolAddress((void**)&simw, g_simw);
    cudaGetSymbolAddress((void**)&ww,   g_ww);
    cudaGetSymbolAddress((void**)&colsum, g_colsum);

    const int MROWS = B_SZ * T_SZ; // 8192

    reset_kernel<<<1, 32>>>();
    rownorm_kernel<<<M_SZ, 256>>>(memory);
    colsum_kernel<<<M_SZ / 256, 256>>>(memory);

    // weight splits (tiled transpose; independent of h)
    split_w_kernel<<<7 * 128, 256>>>(rk_W, wk_W, we_W, wa_W);

    // xz = inputs @ Wx + b  (fp32 FFMA)
    sgemm_kernel<<<dim3(2048 / 128, MROWS / 128), 256>>>(
        inputs, Wx, bvec, xz, 2048, 256);

    // LSTM scan -> h  (128 CTAs x 256 threads, R5-proven)
    lstm_kernel<<<128, 256>>>(xz, Wh, h);

    // split h into bf16 hi/lo
    split_h_kernel<<<MROWS * H_SZ / 256, 256>>>(h);

    // all 7 projection GEMMs via double-buffered mma.sync bf16 split
    mma_proj_kernel<<<7 * 512, 256>>>(rk_b, wk_b, we_b, wa_b, rk, wk, eb, ab);

    // similarity reductions
    sim_kernel<<<R_SZ * B_SZ * T_SZ, 256>>>(rk, memory, sim);
    sim_kernel<<<B_SZ * T_SZ, 256>>>(wk, memory, simw);

    // reads -> out[0:32768)
    softmax_row_kernel<<<R_SZ * B_SZ, 256>>>(sim, colsum, out);
    softmax_row_kernel<<<B_SZ, 256>>>(simw, (const float*)nullptr, ww);

    // new_memory -> out[32768 : ]
    memupd_kernel<<<(B_SZ * M_SZ * M_SZ / 4) / 256, 256>>>(
        eb, ab, memory, out + R_SZ * B_SZ * T_SZ);
}